// round 8
// baseline (speedup 1.0000x reference)
#include <cuda_runtime.h>
#include <cuda.h>
#include <cuda_fp16.h>
#include <cstdint>

// ============================================================================
// Problem dims
// ============================================================================
#define NDIM 4096
#define KDIM 4096
#define ODIM 4096

// GEMM tiling (fp16 single-pass)
#define BM 128
#define BN 128
#define BK 64                      // fp16 elems per K-chunk (128 B rows, SW128)
#define STAGES 3
#define KCHUNKS (KDIM / BK)        // 64

// SMEM layout (dynamic):
//  [0:24)   full barriers (3 x 8B)
//  [1024 + s*32768) stage s: A (16KB) | B (16KB)
#define SMEM_DATA   1024
#define STAGE_BYTES 32768
#define OFF_B       16384
#define SMEM_TOTAL  (SMEM_DATA + STAGES * STAGE_BYTES)   // 99328  (x2 CTAs = 198KB)

// ============================================================================
// Scratch (device globals; no allocation allowed)
// ============================================================================
static __device__ __align__(1024) __half g_Xh[(size_t)NDIM * KDIM];  // 32MB
static __device__ __align__(1024) __half g_Wq[(size_t)ODIM * KDIM];  // 32MB

// ============================================================================
// PTX helpers (base sm_103: TMA + mbarrier + ldmatrix + mma.sync)
// ============================================================================
__device__ __forceinline__ uint32_t smem_u32(const void* p) {
    uint32_t a;
    asm("{ .reg .u64 t; cvta.to.shared.u64 t, %1; cvt.u32.u64 %0, t; }" : "=r"(a) : "l"(p));
    return a;
}

#define MBARRIER_INIT(addr, cnt) \
    asm volatile("mbarrier.init.shared.b64 [%0], %1;" :: "r"((uint32_t)(addr)), "r"((uint32_t)(cnt)) : "memory")

#define MBARRIER_EXPECT_TX(addr, bytes) \
    asm volatile("mbarrier.arrive.expect_tx.shared.b64 _, [%0], %1;" :: "r"((uint32_t)(addr)), "r"((uint32_t)(bytes)) : "memory")

#define MBARRIER_WAIT_PARITY(mbar_smem_addr, phase_parity) do {                                   \
    uint32_t _mbar = (uint32_t)(mbar_smem_addr);                                                  \
    uint32_t _parity = (uint32_t)(phase_parity);                                                  \
    uint32_t _done;                                                                               \
    asm volatile("{\n\t.reg .pred p;\n\t"                                                         \
        "mbarrier.try_wait.parity.acquire.cta.shared::cta.b64 p, [%1], %2;\n\t"                   \
        "selp.b32 %0, 1, 0, p;\n\t}"                                                              \
        : "=r"(_done) : "r"(_mbar), "r"(_parity) : "memory");                                     \
    if (!_done) {                                                                                 \
        asm volatile("{\n\t.reg .pred P1;\n\t"                                                    \
            "WAIT_LOOP_%=:\n\t"                                                                   \
            "mbarrier.try_wait.parity.acquire.cta.shared::cta.b64 P1, [%0], %1, 0x989680;\n\t"    \
            "@P1 bra.uni WAIT_DONE_%=;\n\t"                                                       \
            "bra.uni WAIT_LOOP_%=;\n\t"                                                           \
            "WAIT_DONE_%=:\n\t}"                                                                  \
            :: "r"(_mbar), "r"(_parity) : "memory");                                              \
    }                                                                                             \
} while (0)

__device__ __forceinline__ void tma2d(uint32_t smem_addr, const CUtensorMap* tm,
                                      int cx, int cy, uint32_t mbar) {
    asm volatile(
        "cp.async.bulk.tensor.2d.shared::cta.global.tile.mbarrier::complete_tx::bytes "
        "[%0], [%1, {%2, %3}], [%4];"
        :: "r"(smem_addr), "l"(tm), "r"(cx), "r"(cy), "r"(mbar) : "memory");
}

__device__ __forceinline__ void ldsm4(uint32_t& r0, uint32_t& r1, uint32_t& r2, uint32_t& r3,
                                      uint32_t addr) {
    asm volatile("ldmatrix.sync.aligned.m8n8.x4.shared.b16 {%0,%1,%2,%3}, [%4];"
                 : "=r"(r0), "=r"(r1), "=r"(r2), "=r"(r3) : "r"(addr));
}

__device__ __forceinline__ void mma_f16(float* c, const uint32_t* a, const uint32_t* b) {
    asm volatile(
        "mma.sync.aligned.m16n8k16.row.col.f32.f16.f16.f32 "
        "{%0,%1,%2,%3}, {%4,%5,%6,%7}, {%8,%9}, {%0,%1,%2,%3};"
        : "+f"(c[0]), "+f"(c[1]), "+f"(c[2]), "+f"(c[3])
        : "r"(a[0]), "r"(a[1]), "r"(a[2]), "r"(a[3]), "r"(b[0]), "r"(b[1]));
}

// ============================================================================
// Kernel 1: X (fp32) -> fp16 (single rounding; rel err <= 2^-11)
// ============================================================================
__global__ void __launch_bounds__(256) k_cvt_x(const float4* __restrict__ x,
                                               uint2* __restrict__ xh, int n4) {
    int i = blockIdx.x * blockDim.x + threadIdx.x;
    if (i >= n4) return;
    float4 v = x[i];
    __half2 h01 = __floats2half2_rn(v.x, v.y);
    __half2 h23 = __floats2half2_rn(v.z, v.w);
    uint2 H;
    H.x = *reinterpret_cast<uint32_t*>(&h01);
    H.y = *reinterpret_cast<uint32_t*>(&h23);
    xh[i] = H;
}

// ============================================================================
// Kernel 2: unpack int4 weights -> centered fp16 (q - 8), exact
// ============================================================================
__device__ __forceinline__ uint32_t unpack2h(int b) {
    int qlo = (b & 0xF) - 8;
    int qhi = ((b >> 4) & 0xF) - 8;
    __half2 h = __floats2half2_rn((float)qlo, (float)qhi);
    return *reinterpret_cast<uint32_t*>(&h);
}

__global__ void __launch_bounds__(256) k_cvt_w(const int4* __restrict__ wp,
                                               uint4* __restrict__ wq, int n4) {
    int i = blockIdx.x * blockDim.x + threadIdx.x;
    if (i >= n4) return;
    int4 p = wp[i];
    uint4 o;
    o.x = unpack2h(p.x);
    o.y = unpack2h(p.y);
    o.z = unpack2h(p.z);
    o.w = unpack2h(p.w);
    wq[i] = o;
}

// ============================================================================
// Kernel 3: fp16 mma.sync GEMM, TMA 3-stage pipeline, 2 CTAs/SM.
// CTA 128x128, 256 threads, warp grid 4(m) x 2(n), warp tile 32x64.
// ============================================================================
__global__ void __launch_bounds__(256, 2) gemm_kernel(
    const __grid_constant__ CUtensorMap tmA,
    const __grid_constant__ CUtensorMap tmB,
    const float* __restrict__ scales,
    const float* __restrict__ bias,
    float* __restrict__ out)
{
    extern __shared__ char smem[];
    uint32_t sb = smem_u32(smem);
    int tid = threadIdx.x, wid = tid >> 5, lane = tid & 31;
    int warp_m = wid & 3;          // 0..3 -> 32-row slice
    int warp_n = wid >> 2;         // 0..1 -> 64-col slice

    // Block-swizzled tile mapping (8 row-tiles per group -> wave fits L2)
    const int colTiles = ODIM / BN;        // 32
    const int GROUP = 8;
    int g = blockIdx.x / (GROUP * colTiles);
    int r = blockIdx.x % (GROUP * colTiles);
    int rt = g * GROUP + (r % GROUP);
    int ct = r / GROUP;
    int rowBase = rt * BM;
    int colBase = ct * BN;

    if (tid == 0) {
        #pragma unroll
        for (int s = 0; s < STAGES; s++) MBARRIER_INIT(sb + 8 * s, 1);
    }
    __syncthreads();

    // Prologue: prefetch chunks 0..STAGES-1
    if (tid == 0) {
        #pragma unroll
        for (int p = 0; p < STAGES; p++) {
            uint32_t fb = sb + 8 * p;
            MBARRIER_EXPECT_TX(fb, (uint32_t)STAGE_BYTES);
            uint32_t st = sb + SMEM_DATA + p * STAGE_BYTES;
            tma2d(st,         &tmA, p * BK, rowBase, fb);
            tma2d(st + OFF_B, &tmB, p * BK, colBase, fb);
        }
    }

    // ldmatrix addressing: 128 B rows, SW128 swizzle = col ^ ((row&7)<<4)
    uint32_t rowA = (uint32_t)(warp_m * 32 + (lane & 15));
    uint32_t rowB = (uint32_t)(warp_n * 64 + (lane & 15));
    uint32_t ksel = (uint32_t)((lane >> 4) << 4);   // 0 or 16 bytes
    uint32_t aRel0 = rowA * 128;
    uint32_t bRel0 = rowB * 128;
    uint32_t xorA = (rowA & 7) << 4;
    uint32_t xorB = (rowB & 7) << 4;

    float acc[2][8][4];
    #pragma unroll
    for (int i = 0; i < 2; i++)
        #pragma unroll
        for (int j = 0; j < 8; j++)
            #pragma unroll
            for (int k = 0; k < 4; k++) acc[i][j][k] = 0.0f;

    #pragma unroll 1
    for (int i = 0; i < KCHUNKS; i++) {
        int s = i % STAGES;
        MBARRIER_WAIT_PARITY(sb + 8 * s, (i / STAGES) & 1);
        uint32_t sA = sb + SMEM_DATA + s * STAGE_BYTES;
        uint32_t sB = sA + OFF_B;

        #pragma unroll
        for (int ks = 0; ks < 4; ks++) {          // k16 steps in the 64-elem chunk
            uint32_t kb = (uint32_t)(ks * 32) + ksel;
            uint32_t kbA = kb ^ xorA;
            uint32_t kbB = kb ^ xorB;

            // B fragments: 4x ldsm.x4 covering n64 x k16
            uint32_t bf[8][2];
            #pragma unroll
            for (int t = 0; t < 4; t++)
                ldsm4(bf[2 * t][0], bf[2 * t + 1][0], bf[2 * t][1], bf[2 * t + 1][1],
                      sB + bRel0 + (uint32_t)(t * 16 * 128) + kbB);

            // A fragments: 2x ldsm.x4 covering m32 x k16
            uint32_t af[2][4];
            #pragma unroll
            for (int mt = 0; mt < 2; mt++)
                ldsm4(af[mt][0], af[mt][1], af[mt][2], af[mt][3],
                      sA + aRel0 + (uint32_t)(mt * 16 * 128) + kbA);

            #pragma unroll
            for (int mt = 0; mt < 2; mt++)
                #pragma unroll
                for (int nt = 0; nt < 8; nt++)
                    mma_f16(acc[mt][nt], af[mt], bf[nt]);
        }

        __syncthreads();
        int pc = i + STAGES;
        if (tid == 0 && pc < KCHUNKS) {
            uint32_t fb = sb + 8 * s;
            MBARRIER_EXPECT_TX(fb, (uint32_t)STAGE_BYTES);
            uint32_t st = sb + SMEM_DATA + s * STAGE_BYTES;
            tma2d(st,         &tmA, pc * BK, rowBase, fb);
            tma2d(st + OFF_B, &tmB, pc * BK, colBase, fb);
        }
    }

    // Epilogue: out = acc * scale[col] + bias[col]
    int row0 = rowBase + warp_m * 32 + (lane >> 2);
    int col0 = colBase + warp_n * 64 + (lane & 3) * 2;
    #pragma unroll
    for (int nt = 0; nt < 8; nt++) {
        int c = col0 + nt * 8;
        float s0 = __ldg(scales + c), s1 = __ldg(scales + c + 1);
        float b0 = __ldg(bias + c),   b1 = __ldg(bias + c + 1);
        #pragma unroll
        for (int mt = 0; mt < 2; mt++) {
            int rr = row0 + mt * 16;
            float2 v0 = make_float2(fmaf(acc[mt][nt][0], s0, b0),
                                    fmaf(acc[mt][nt][1], s1, b1));
            float2 v1 = make_float2(fmaf(acc[mt][nt][2], s0, b0),
                                    fmaf(acc[mt][nt][3], s1, b1));
            *reinterpret_cast<float2*>(out + (size_t)rr * ODIM + c) = v0;
            *reinterpret_cast<float2*>(out + (size_t)(rr + 8) * ODIM + c) = v1;
        }
    }
}

// ============================================================================
// Host side
// ============================================================================
typedef CUresult (*PFN_encodeTiled)(
    CUtensorMap*, CUtensorMapDataType, cuuint32_t, void*,
    const cuuint64_t*, const cuuint64_t*, const cuuint32_t*, const cuuint32_t*,
    CUtensorMapInterleave, CUtensorMapSwizzle, CUtensorMapL2promotion, CUtensorMapFloatOOBfill);

static PFN_encodeTiled get_encoder() {
    void* fn = nullptr;
    cudaDriverEntryPointQueryResult qr;
    cudaGetDriverEntryPointByVersion("cuTensorMapEncodeTiled", &fn, 12000,
                                     cudaEnableDefault, &qr);
    return (PFN_encodeTiled)fn;
}

static void encode_f16_2d(PFN_encodeTiled enc, CUtensorMap* tm, void* base,
                          uint64_t d0, uint64_t d1, uint32_t b0, uint32_t b1) {
    cuuint64_t gd[2] = {d0, d1};
    cuuint64_t gs[1] = {d0 * 2};   // row stride, bytes
    cuuint32_t box[2] = {b0, b1};
    cuuint32_t es[2] = {1, 1};
    enc(tm, CU_TENSOR_MAP_DATA_TYPE_FLOAT16, 2, base, gd, gs, box, es,
        CU_TENSOR_MAP_INTERLEAVE_NONE, CU_TENSOR_MAP_SWIZZLE_128B,
        CU_TENSOR_MAP_L2_PROMOTION_L2_128B, CU_TENSOR_MAP_FLOAT_OOB_FILL_NONE);
}

extern "C" void kernel_launch(void* const* d_in, const int* in_sizes, int n_in,
                              void* d_out, int out_size) {
    const float* x  = (const float*)d_in[0];
    const int*   wp = (const int*)d_in[1];
    const float* ws = (const float*)d_in[2];
    const float* bs = (const float*)d_in[3];
    float* out = (float*)d_out;

    void *pXh, *pWq;
    cudaGetSymbolAddress(&pXh, g_Xh);
    cudaGetSymbolAddress(&pWq, g_Wq);

    // 1) precompute: X -> fp16, unpack W to centered fp16
    {
        int n4 = NDIM * KDIM / 4;
        k_cvt_x<<<(n4 + 255) / 256, 256>>>((const float4*)x, (uint2*)pXh, n4);
    }
    {
        int n4 = (ODIM * (KDIM / 2)) / 4;
        k_cvt_w<<<(n4 + 255) / 256, 256>>>((const int4*)wp, (uint4*)pWq, n4);
    }

    // 2) TMA descriptors
    PFN_encodeTiled enc = get_encoder();
    CUtensorMap tA, tB;
    encode_f16_2d(enc, &tA, pXh, KDIM, NDIM, BK, BM);
    encode_f16_2d(enc, &tB, pWq, KDIM, ODIM, BK, BN);

    // 3) GEMM
    cudaFuncSetAttribute(gemm_kernel, cudaFuncAttributeMaxDynamicSharedMemorySize, SMEM_TOTAL);
    int grid = (NDIM / BM) * (ODIM / BN);   // 1024
    gemm_kernel<<<grid, 256, SMEM_TOTAL>>>(tA, tB, ws, bs, out);
}

// round 10
// speedup vs baseline: 1.2112x; 1.2112x over previous
#include <cuda_runtime.h>
#include <cuda.h>
#include <cuda_fp16.h>
#include <cstdint>

// ============================================================================
// Problem dims
// ============================================================================
#define NDIM 4096
#define KDIM 4096
#define ODIM 4096

// GEMM tiling (fp16 single-pass)
#define BM 128
#define BN 256
#define BK 64                      // fp16 elems per K-chunk (128 B rows, SW128)
#define STAGES 4
#define KCHUNKS (KDIM / BK)        // 64

// SMEM layout (dynamic):
//  [0:32)   full barriers (4 x 8B)
//  [1024 + s*49152) stage s: A (16KB) | B (32KB)
#define SMEM_DATA   1024
#define STAGE_BYTES 49152
#define OFF_B       16384
#define SMEM_TOTAL  (SMEM_DATA + STAGES * STAGE_BYTES)   // 197632 (1 CTA/SM)

// ============================================================================
// Scratch (device globals; no allocation allowed)
// ============================================================================
static __device__ __align__(1024) __half g_Xh[(size_t)NDIM * KDIM];  // 32MB
static __device__ __align__(1024) __half g_Wq[(size_t)ODIM * KDIM];  // 32MB

// ============================================================================
// PTX helpers (base sm_103: TMA + mbarrier + ldmatrix + mma.sync)
// ============================================================================
__device__ __forceinline__ uint32_t smem_u32(const void* p) {
    uint32_t a;
    asm("{ .reg .u64 t; cvta.to.shared.u64 t, %1; cvt.u32.u64 %0, t; }" : "=r"(a) : "l"(p));
    return a;
}

#define MBARRIER_INIT(addr, cnt) \
    asm volatile("mbarrier.init.shared.b64 [%0], %1;" :: "r"((uint32_t)(addr)), "r"((uint32_t)(cnt)) : "memory")

#define MBARRIER_EXPECT_TX(addr, bytes) \
    asm volatile("mbarrier.arrive.expect_tx.shared.b64 _, [%0], %1;" :: "r"((uint32_t)(addr)), "r"((uint32_t)(bytes)) : "memory")

#define MBARRIER_WAIT_PARITY(mbar_smem_addr, phase_parity) do {                                   \
    uint32_t _mbar = (uint32_t)(mbar_smem_addr);                                                  \
    uint32_t _parity = (uint32_t)(phase_parity);                                                  \
    uint32_t _done;                                                                               \
    asm volatile("{\n\t.reg .pred p;\n\t"                                                         \
        "mbarrier.try_wait.parity.acquire.cta.shared::cta.b64 p, [%1], %2;\n\t"                   \
        "selp.b32 %0, 1, 0, p;\n\t}"                                                              \
        : "=r"(_done) : "r"(_mbar), "r"(_parity) : "memory");                                     \
    if (!_done) {                                                                                 \
        asm volatile("{\n\t.reg .pred P1;\n\t"                                                    \
            "WAIT_LOOP_%=:\n\t"                                                                   \
            "mbarrier.try_wait.parity.acquire.cta.shared::cta.b64 P1, [%0], %1, 0x989680;\n\t"    \
            "@P1 bra.uni WAIT_DONE_%=;\n\t"                                                       \
            "bra.uni WAIT_LOOP_%=;\n\t"                                                           \
            "WAIT_DONE_%=:\n\t}"                                                                  \
            :: "r"(_mbar), "r"(_parity) : "memory");                                              \
    }                                                                                             \
} while (0)

__device__ __forceinline__ void tma2d(uint32_t smem_addr, const CUtensorMap* tm,
                                      int cx, int cy, uint32_t mbar) {
    asm volatile(
        "cp.async.bulk.tensor.2d.shared::cta.global.tile.mbarrier::complete_tx::bytes "
        "[%0], [%1, {%2, %3}], [%4];"
        :: "r"(smem_addr), "l"(tm), "r"(cx), "r"(cy), "r"(mbar) : "memory");
}

__device__ __forceinline__ void ldsm4(uint32_t& r0, uint32_t& r1, uint32_t& r2, uint32_t& r3,
                                      uint32_t addr) {
    asm volatile("ldmatrix.sync.aligned.m8n8.x4.shared.b16 {%0,%1,%2,%3}, [%4];"
                 : "=r"(r0), "=r"(r1), "=r"(r2), "=r"(r3) : "r"(addr));
}

__device__ __forceinline__ void mma_f16(float* c, const uint32_t* a, const uint32_t* b) {
    asm volatile(
        "mma.sync.aligned.m16n8k16.row.col.f32.f16.f16.f32 "
        "{%0,%1,%2,%3}, {%4,%5,%6,%7}, {%8,%9}, {%0,%1,%2,%3};"
        : "+f"(c[0]), "+f"(c[1]), "+f"(c[2]), "+f"(c[3])
        : "r"(a[0]), "r"(a[1]), "r"(a[2]), "r"(a[3]), "r"(b[0]), "r"(b[1]));
}

// ============================================================================
// Kernel 1: X (fp32) -> fp16 (single rounding; rel err <= 2^-11)
// ============================================================================
__global__ void __launch_bounds__(256) k_cvt_x(const float4* __restrict__ x,
                                               uint2* __restrict__ xh, int n4) {
    int i = blockIdx.x * blockDim.x + threadIdx.x;
    if (i >= n4) return;
    float4 v = x[i];
    __half2 h01 = __floats2half2_rn(v.x, v.y);
    __half2 h23 = __floats2half2_rn(v.z, v.w);
    uint2 H;
    H.x = *reinterpret_cast<uint32_t*>(&h01);
    H.y = *reinterpret_cast<uint32_t*>(&h23);
    xh[i] = H;
}

// ============================================================================
// Kernel 2: unpack int4 weights -> centered fp16 (q - 8), exact
// ============================================================================
__device__ __forceinline__ uint32_t unpack2h(int b) {
    int qlo = (b & 0xF) - 8;
    int qhi = ((b >> 4) & 0xF) - 8;
    __half2 h = __floats2half2_rn((float)qlo, (float)qhi);
    return *reinterpret_cast<uint32_t*>(&h);
}

__global__ void __launch_bounds__(256) k_cvt_w(const int4* __restrict__ wp,
                                               uint4* __restrict__ wq, int n4) {
    int i = blockIdx.x * blockDim.x + threadIdx.x;
    if (i >= n4) return;
    int4 p = wp[i];
    uint4 o;
    o.x = unpack2h(p.x);
    o.y = unpack2h(p.y);
    o.z = unpack2h(p.z);
    o.w = unpack2h(p.w);
    wq[i] = o;
}

// ============================================================================
// Kernel 3: fp16 mma.sync GEMM, TMA 4-stage pipeline, 1 CTA/SM.
// CTA 128x256, 256 threads, warp grid 2(m) x 4(n), warp tile 64x64.
// 33% less smem-crossbar traffic per FLOP vs 32x64 warp tiles.
// ============================================================================
__global__ void __launch_bounds__(256, 1) gemm_kernel(
    const __grid_constant__ CUtensorMap tmA,
    const __grid_constant__ CUtensorMap tmB,
    const float* __restrict__ scales,
    const float* __restrict__ bias,
    float* __restrict__ out)
{
    extern __shared__ char smem[];
    uint32_t sb = smem_u32(smem);
    int tid = threadIdx.x, wid = tid >> 5, lane = tid & 31;
    int warp_m = wid & 1;          // 0..1 -> 64-row slice
    int warp_n = wid >> 1;         // 0..3 -> 64-col slice

    // Block-swizzled tile mapping (8 row-tiles per group -> wave fits L2)
    const int colTiles = ODIM / BN;        // 16
    const int GROUP = 8;
    int g = blockIdx.x / (GROUP * colTiles);
    int r = blockIdx.x % (GROUP * colTiles);
    int rt = g * GROUP + (r % GROUP);
    int ct = r / GROUP;
    int rowBase = rt * BM;
    int colBase = ct * BN;

    if (tid == 0) {
        #pragma unroll
        for (int s = 0; s < STAGES; s++) MBARRIER_INIT(sb + 8 * s, 1);
    }
    __syncthreads();

    // Prologue: prefetch chunks 0..STAGES-1
    if (tid == 0) {
        #pragma unroll
        for (int p = 0; p < STAGES; p++) {
            uint32_t fb = sb + 8 * p;
            MBARRIER_EXPECT_TX(fb, (uint32_t)STAGE_BYTES);
            uint32_t st = sb + SMEM_DATA + p * STAGE_BYTES;
            tma2d(st,         &tmA, p * BK, rowBase, fb);
            tma2d(st + OFF_B, &tmB, p * BK, colBase, fb);
        }
    }

    // ldmatrix addressing: 128 B rows, SW128 swizzle = col ^ ((row&7)<<4)
    uint32_t rowA = (uint32_t)(warp_m * 64 + (lane & 15));
    uint32_t rowB = (uint32_t)(warp_n * 64 + (lane & 15));
    uint32_t ksel = (uint32_t)((lane >> 4) << 4);   // 0 or 16 bytes
    uint32_t aRel0 = rowA * 128;
    uint32_t bRel0 = rowB * 128;
    uint32_t xorA = (rowA & 7) << 4;
    uint32_t xorB = (rowB & 7) << 4;

    float acc[4][8][4];
    #pragma unroll
    for (int i = 0; i < 4; i++)
        #pragma unroll
        for (int j = 0; j < 8; j++)
            #pragma unroll
            for (int k = 0; k < 4; k++) acc[i][j][k] = 0.0f;

    #pragma unroll 1
    for (int i = 0; i < KCHUNKS; i++) {
        int s = i % STAGES;
        MBARRIER_WAIT_PARITY(sb + 8 * s, (i / STAGES) & 1);
        uint32_t sA = sb + SMEM_DATA + s * STAGE_BYTES;
        uint32_t sB = sA + OFF_B;

        #pragma unroll
        for (int ks = 0; ks < 4; ks++) {          // k16 steps in the 64-elem chunk
            uint32_t kb = (uint32_t)(ks * 32) + ksel;
            uint32_t kbA = kb ^ xorA;
            uint32_t kbB = kb ^ xorB;

            // B fragments: 4x ldsm.x4 covering n64 x k16
            uint32_t bf[8][2];
            #pragma unroll
            for (int t = 0; t < 4; t++)
                ldsm4(bf[2 * t][0], bf[2 * t + 1][0], bf[2 * t][1], bf[2 * t + 1][1],
                      sB + bRel0 + (uint32_t)(t * 16 * 128) + kbB);

            // A fragments: 4x ldsm.x4 covering m64 x k16
            uint32_t af[4][4];
            #pragma unroll
            for (int mt = 0; mt < 4; mt++)
                ldsm4(af[mt][0], af[mt][1], af[mt][2], af[mt][3],
                      sA + aRel0 + (uint32_t)(mt * 16 * 128) + kbA);

            #pragma unroll
            for (int mt = 0; mt < 4; mt++)
                #pragma unroll
                for (int nt = 0; nt < 8; nt++)
                    mma_f16(acc[mt][nt], af[mt], bf[nt]);
        }

        __syncthreads();
        int pc = i + STAGES;
        if (tid == 0 && pc < KCHUNKS) {
            uint32_t fb = sb + 8 * s;
            MBARRIER_EXPECT_TX(fb, (uint32_t)STAGE_BYTES);
            uint32_t st = sb + SMEM_DATA + s * STAGE_BYTES;
            tma2d(st,         &tmA, pc * BK, rowBase, fb);
            tma2d(st + OFF_B, &tmB, pc * BK, colBase, fb);
        }
    }

    // Epilogue: out = acc * scale[col] + bias[col]
    int row0 = rowBase + warp_m * 64 + (lane >> 2);
    int col0 = colBase + warp_n * 64 + (lane & 3) * 2;
    #pragma unroll
    for (int nt = 0; nt < 8; nt++) {
        int c = col0 + nt * 8;
        float s0 = __ldg(scales + c), s1 = __ldg(scales + c + 1);
        float b0 = __ldg(bias + c),   b1 = __ldg(bias + c + 1);
        #pragma unroll
        for (int mt = 0; mt < 4; mt++) {
            int rr = row0 + mt * 16;
            float2 v0 = make_float2(fmaf(acc[mt][nt][0], s0, b0),
                                    fmaf(acc[mt][nt][1], s1, b1));
            float2 v1 = make_float2(fmaf(acc[mt][nt][2], s0, b0),
                                    fmaf(acc[mt][nt][3], s1, b1));
            *reinterpret_cast<float2*>(out + (size_t)rr * ODIM + c) = v0;
            *reinterpret_cast<float2*>(out + (size_t)(rr + 8) * ODIM + c) = v1;
        }
    }
}

// ============================================================================
// Host side
// ============================================================================
typedef CUresult (*PFN_encodeTiled)(
    CUtensorMap*, CUtensorMapDataType, cuuint32_t, void*,
    const cuuint64_t*, const cuuint64_t*, const cuuint32_t*, const cuuint32_t*,
    CUtensorMapInterleave, CUtensorMapSwizzle, CUtensorMapL2promotion, CUtensorMapFloatOOBfill);

static PFN_encodeTiled get_encoder() {
    void* fn = nullptr;
    cudaDriverEntryPointQueryResult qr;
    cudaGetDriverEntryPointByVersion("cuTensorMapEncodeTiled", &fn, 12000,
                                     cudaEnableDefault, &qr);
    return (PFN_encodeTiled)fn;
}

static void encode_f16_2d(PFN_encodeTiled enc, CUtensorMap* tm, void* base,
                          uint64_t d0, uint64_t d1, uint32_t b0, uint32_t b1) {
    cuuint64_t gd[2] = {d0, d1};
    cuuint64_t gs[1] = {d0 * 2};   // row stride, bytes
    cuuint32_t box[2] = {b0, b1};
    cuuint32_t es[2] = {1, 1};
    enc(tm, CU_TENSOR_MAP_DATA_TYPE_FLOAT16, 2, base, gd, gs, box, es,
        CU_TENSOR_MAP_INTERLEAVE_NONE, CU_TENSOR_MAP_SWIZZLE_128B,
        CU_TENSOR_MAP_L2_PROMOTION_L2_128B, CU_TENSOR_MAP_FLOAT_OOB_FILL_NONE);
}

extern "C" void kernel_launch(void* const* d_in, const int* in_sizes, int n_in,
                              void* d_out, int out_size) {
    const float* x  = (const float*)d_in[0];
    const int*   wp = (const int*)d_in[1];
    const float* ws = (const float*)d_in[2];
    const float* bs = (const float*)d_in[3];
    float* out = (float*)d_out;

    void *pXh, *pWq;
    cudaGetSymbolAddress(&pXh, g_Xh);
    cudaGetSymbolAddress(&pWq, g_Wq);

    // 1) precompute: X -> fp16, unpack W to centered fp16
    {
        int n4 = NDIM * KDIM / 4;
        k_cvt_x<<<(n4 + 255) / 256, 256>>>((const float4*)x, (uint2*)pXh, n4);
    }
    {
        int n4 = (ODIM * (KDIM / 2)) / 4;
        k_cvt_w<<<(n4 + 255) / 256, 256>>>((const int4*)wp, (uint4*)pWq, n4);
    }

    // 2) TMA descriptors
    PFN_encodeTiled enc = get_encoder();
    CUtensorMap tA, tB;
    encode_f16_2d(enc, &tA, pXh, KDIM, NDIM, BK, BM);
    encode_f16_2d(enc, &tB, pWq, KDIM, ODIM, BK, BN);

    // 3) GEMM
    cudaFuncSetAttribute(gemm_kernel, cudaFuncAttributeMaxDynamicSharedMemorySize, SMEM_TOTAL);
    int grid = (NDIM / BM) * (ODIM / BN);   // 512
    gemm_kernel<<<grid, 256, SMEM_TOTAL>>>(tA, tB, ws, bs, out);
}